// round 16
// baseline (speedup 1.0000x reference)
#include <cuda_runtime.h>
#include <cstdint>

// Problem constants (fixed shapes)
#define VF    128            // V*F = 8*16
#define CCH   1024
#define HH    14
#define WW    14
#define NBOX  768
#define GG    8              // grid = OUT_SIZE+1
#define OUTS  7
#define CHT   32             // channels per block tile
#define TILES (CCH / CHT)    // 32
#define BOXPB 8              // boxes per roi block
#define SCALE (1.0f/16.0f)

#define ROI_BLOCKS   ((NBOX/BOXPB) * TILES)              // 3072
#define SNODE_BLOCKS ((VF * CCH) / 32)                   // 4096 (4 planes/warp)

#define ROI_COUNT   ((size_t)NBOX * CCH * OUTS * OUTS)   // 38,535,168
#define SNODE_OFF   (ROI_COUNT)
#define FAKE_OFF    (SNODE_OFF + (size_t)VF * CCH)       // 38,666,240

__device__ __forceinline__ void stcs4(float4* p, float4 v) {
    asm volatile("st.global.cs.v4.f32 [%0], {%1,%2,%3,%4};"
                 :: "l"(p), "f"(v.x), "f"(v.y), "f"(v.z), "f"(v.w) : "memory");
}
__device__ __forceinline__ void stcs2(float2* p, float2 v) {
    asm volatile("st.global.cs.v2.f32 [%0], {%1,%2};"
                 :: "l"(p), "f"(v.x), "f"(v.y) : "memory");
}
__device__ __forceinline__ void stcs1(float* p, float v) {
    asm volatile("st.global.cs.f32 [%0], %1;" :: "l"(p), "f"(v) : "memory");
}

// ---------------------------------------------------------------------------
// One box for one warp: direct-LDG bilinear compute (no input staging).
// Feature rows are register-cached; row-switch branches are warp-uniform.
// ---------------------------------------------------------------------------
__device__ __forceinline__ void roi_one_box(
    const float* __restrict__ feat,
    const float* __restrict__ boxes,
    const int*   __restrict__ fidx,
    float*       __restrict__ out,
    float* outsm,
    int n, int c0, int cw, int lane)
{
    const float bx1 = boxes[n*4+0]*SCALE, by1 = boxes[n*4+1]*SCALE;
    const float bx2 = boxes[n*4+2]*SCALE, by2 = boxes[n*4+3]*SCALE;

    const int gx    = lane & 7;
    const int chsub = lane >> 3;
    const int ch    = cw + chsub;

    const float* fp = feat + ((size_t)fidx[n] * CCH + c0 + ch) * (HH*WW);

    const float xs0 = fminf(fmaxf(bx1 + (float)gx * (1.0f/7.0f) * (bx2 - bx1),
                                  0.0f), (float)(WW-1));
    const int   xa  = (int)floorf(xs0);
    const int   xb  = min(xa + 1, WW-1);
    const float wx  = xs0 - (float)xa;

    int   curA = -1, curB = -1;
    float a0 = 0.f, a1 = 0.f, b0 = 0.f, b1 = 0.f;
    float xs_prev = 0.f;

    #pragma unroll
    for (int gy = 0; gy < GG; ++gy) {
        const float ys = fminf(fmaxf(by1 + (float)gy * (1.0f/7.0f) * (by2 - by1),
                                     0.0f), (float)(HH-1));
        const int y0i = (int)floorf(ys);
        const int y1i = min(y0i + 1, HH-1);
        const float wy = ys - (float)y0i;
        if (y0i != curA) {                 // warp-uniform branch
            if (y0i == curB) { a0 = b0; a1 = b1; }
            else             { a0 = fp[y0i*WW + xa]; a1 = fp[y0i*WW + xb]; }
            curA = y0i;
        }
        if (y1i != curB) {                 // warp-uniform branch
            b0 = fp[y1i*WW + xa]; b1 = fp[y1i*WW + xb];
            curB = y1i;
        }
        const float top = a0 + wx * (a1 - a0);
        const float bot = b0 + wx * (b1 - b0);
        const float g   = top + wy * (bot - top);
        // x-pool: neighbor gx+1 within the 8-lane group
        const float gr   = __shfl_down_sync(0xFFFFFFFFu, g, 1, 8);
        const float xsum = g + gr;
        if (gy > 0 && gx < OUTS)
            outsm[ch * (OUTS*OUTS) + (gy-1) * OUTS + gx] = 0.25f * (xs_prev + xsum);
        xs_prev = xsum;
    }
    __syncwarp();

    // ---- store: warp-local vectorized streaming copy of its 4 channels ----
    {
        const float4* src4 = (const float4*)(outsm + cw * (OUTS*OUTS));
        float4*       dst4 = (float4*)(out + ((size_t)n * CCH + c0 + cw) * (OUTS*OUTS));
        #pragma unroll
        for (int i = lane; i < 49; i += 32)          // 4*49 floats = 49 float4
            stcs4(dst4 + i, src4[i]);
        __syncwarp();                                 // outsm reuse safety
    }
}

// ---------------------------------------------------------------------------
// Fused kernel. Blocks [0, ROI_BLOCKS): RoIAlignAvg, 8 boxes sequentially per
// block, direct-LDG compute, fully warp-independent (no __syncthreads).
// Remaining blocks: s_node mean + fake_h_s slice, 4 planes per warp,
// vectorized: sum via float4 loads, fake slice via float2 store units.
// ---------------------------------------------------------------------------
__global__ __launch_bounds__(256, 8) void fused_kernel(
    const float* __restrict__ feat,
    const float* __restrict__ boxes,
    const int*   __restrict__ fidx,
    float*       __restrict__ out)
{
    extern __shared__ float sm[];

    if (blockIdx.x >= ROI_BLOCKS) {
        // ---------------- snode + fake_h_s branch (4 planes/warp) ---------
        const int warp = threadIdx.x >> 5;
        const int lane = threadIdx.x & 31;
        const size_t p0 = (size_t)(blockIdx.x - ROI_BLOCKS) * 32 + warp * 4;

        #pragma unroll
        for (int pp = 0; pp < 4; ++pp) {
            const size_t planeidx = p0 + pp;
            const float* src  = feat + planeidx * (HH*WW);
            float*       fake = out + FAKE_OFF + planeidx * 144;

            // ---- sum via float4 (196 floats = 49 float4, 16B aligned) ----
            const float4* s4 = (const float4*)src;
            float4 v = s4[lane];                      // lane < 32 < 49
            float sum = (v.x + v.y) + (v.z + v.w);
            if (lane < 17) {
                float4 w = s4[lane + 32];
                sum += (w.x + w.y) + (w.z + w.w);
            }
            #pragma unroll
            for (int o = 16; o; o >>= 1)
                sum += __shfl_down_sync(0xFFFFFFFFu, sum, o);
            if (lane == 0)
                stcs1(out + SNODE_OFF + planeidx, sum * (1.0f / 196.0f));

            // ---- fake slice via 72 float2 units (12 rows x 6) ----
            #pragma unroll
            for (int k = 0; k < 3; ++k) {
                const int u = lane + k * 32;
                if (u < 72) {
                    const int row = u / 6;            // 0..11
                    const int cx  = (u - row * 6) * 2;  // 0,2,..,10
                    const int so  = (row + 1) * WW + 1 + cx;
                    float2 val;
                    val.x = src[so];
                    val.y = src[so + 1];
                    stcs2((float2*)(fake + row * 12 + cx), val);
                }
            }
        }
        return;
    }

    // -------------------------- RoI branch (8 boxes, sequential) -----------
    float* outsm = sm;                     // CHT * 49 floats (6,272 B)

    const int tid  = threadIdx.x;
    const int warp = tid >> 5, lane = tid & 31;
    const int grp  = blockIdx.x / TILES;
    const int c0   = (blockIdx.x % TILES) * CHT;
    const int cw   = warp * 4;             // warp's first channel in tile

    #pragma unroll
    for (int i = 0; i < BOXPB; ++i)
        roi_one_box(feat, boxes, fidx, out, outsm, grp*BOXPB + i, c0, cw, lane);
}

// ---------------------------------------------------------------------------
extern "C" void kernel_launch(void* const* d_in, const int* in_sizes, int n_in,
                              void* d_out, int out_size)
{
    const float* feat  = (const float*)d_in[0];
    const float* boxes = (const float*)d_in[1];
    const int*   fidx  = (const int*)d_in[2];
    float*       out   = (float*)d_out;

    const int roi_smem = (CHT * OUTS * OUTS) * (int)sizeof(float); // 6,272 B
    cudaFuncSetAttribute(fused_kernel,
                         cudaFuncAttributeMaxDynamicSharedMemorySize, roi_smem);

    fused_kernel<<<ROI_BLOCKS + SNODE_BLOCKS, 256, roi_smem>>>(feat, boxes, fidx, out);
}

// round 17
// speedup vs baseline: 1.0447x; 1.0447x over previous
#include <cuda_runtime.h>
#include <cstdint>

// Problem constants (fixed shapes)
#define VF    128            // V*F = 8*16
#define CCH   1024
#define HH    14
#define WW    14
#define NBOX  768
#define GG    8              // grid = OUT_SIZE+1
#define OUTS  7
#define CHT   32             // channels per block tile
#define TILES (CCH / CHT)    // 32
#define BOXPB 4              // boxes per roi block (R15 optimum)
#define SCALE (1.0f/16.0f)

#define ROI_BLOCKS   ((NBOX/BOXPB) * TILES)              // 6144
#define SNODE_BLOCKS ((VF * CCH) / 16)                   // 8192 (2 planes/warp)

#define ROI_COUNT   ((size_t)NBOX * CCH * OUTS * OUTS)   // 38,535,168
#define SNODE_OFF   (ROI_COUNT)
#define FAKE_OFF    (SNODE_OFF + (size_t)VF * CCH)       // 38,666,240

__device__ __forceinline__ void stcs4(float4* p, float4 v) {
    asm volatile("st.global.cs.v4.f32 [%0], {%1,%2,%3,%4};"
                 :: "l"(p), "f"(v.x), "f"(v.y), "f"(v.z), "f"(v.w) : "memory");
}
__device__ __forceinline__ void stcs2(float2* p, float2 v) {
    asm volatile("st.global.cs.v2.f32 [%0], {%1,%2};"
                 :: "l"(p), "f"(v.x), "f"(v.y) : "memory");
}
__device__ __forceinline__ void stcs1(float* p, float v) {
    asm volatile("st.global.cs.f32 [%0], %1;" :: "l"(p), "f"(v) : "memory");
}

// ---------------------------------------------------------------------------
// One box for one warp: direct-LDG bilinear compute (no input staging).
// Feature rows are register-cached; row-switch branches are warp-uniform.
// All feature reads via __ldg (read-only path).
// ---------------------------------------------------------------------------
__device__ __forceinline__ void roi_one_box(
    const float* __restrict__ feat,
    const float* __restrict__ boxes,
    const int*   __restrict__ fidx,
    float*       __restrict__ out,
    float* outsm,
    int n, int c0, int cw, int lane)
{
    const float bx1 = __ldg(boxes + n*4+0)*SCALE, by1 = __ldg(boxes + n*4+1)*SCALE;
    const float bx2 = __ldg(boxes + n*4+2)*SCALE, by2 = __ldg(boxes + n*4+3)*SCALE;

    const int gx    = lane & 7;
    const int chsub = lane >> 3;
    const int ch    = cw + chsub;

    const float* fp = feat + ((size_t)__ldg(fidx + n) * CCH + c0 + ch) * (HH*WW);

    const float xs0 = fminf(fmaxf(bx1 + (float)gx * (1.0f/7.0f) * (bx2 - bx1),
                                  0.0f), (float)(WW-1));
    const int   xa  = (int)floorf(xs0);
    const int   xb  = min(xa + 1, WW-1);
    const float wx  = xs0 - (float)xa;

    int   curA = -1, curB = -1;
    float a0 = 0.f, a1 = 0.f, b0 = 0.f, b1 = 0.f;
    float xs_prev = 0.f;

    #pragma unroll
    for (int gy = 0; gy < GG; ++gy) {
        const float ys = fminf(fmaxf(by1 + (float)gy * (1.0f/7.0f) * (by2 - by1),
                                     0.0f), (float)(HH-1));
        const int y0i = (int)floorf(ys);
        const int y1i = min(y0i + 1, HH-1);
        const float wy = ys - (float)y0i;
        if (y0i != curA) {                 // warp-uniform branch
            if (y0i == curB) { a0 = b0; a1 = b1; }
            else             { a0 = __ldg(fp + y0i*WW + xa); a1 = __ldg(fp + y0i*WW + xb); }
            curA = y0i;
        }
        if (y1i != curB) {                 // warp-uniform branch
            b0 = __ldg(fp + y1i*WW + xa); b1 = __ldg(fp + y1i*WW + xb);
            curB = y1i;
        }
        const float top = a0 + wx * (a1 - a0);
        const float bot = b0 + wx * (b1 - b0);
        const float g   = top + wy * (bot - top);
        // x-pool: neighbor gx+1 within the 8-lane group
        const float gr   = __shfl_down_sync(0xFFFFFFFFu, g, 1, 8);
        const float xsum = g + gr;
        if (gy > 0 && gx < OUTS)
            outsm[ch * (OUTS*OUTS) + (gy-1) * OUTS + gx] = 0.25f * (xs_prev + xsum);
        xs_prev = xsum;
    }
    __syncwarp();

    // ---- store: warp-local vectorized streaming copy of its 4 channels ----
    {
        const float4* src4 = (const float4*)(outsm + cw * (OUTS*OUTS));
        float4*       dst4 = (float4*)(out + ((size_t)n * CCH + c0 + cw) * (OUTS*OUTS));
        #pragma unroll
        for (int i = lane; i < 49; i += 32)          // 4*49 floats = 49 float4
            stcs4(dst4 + i, src4[i]);
        __syncwarp();                                 // outsm reuse safety
    }
}

// ---------------------------------------------------------------------------
// Fused kernel. Blocks [0, ROI_BLOCKS): RoIAlignAvg, 4 boxes sequentially per
// block, direct-LDG compute, fully warp-independent (no __syncthreads).
// Remaining blocks: s_node mean + fake_h_s slice, 2 planes per warp,
// vectorized: sum via float4 loads, fake slice via float2 store units.
// ---------------------------------------------------------------------------
__global__ __launch_bounds__(256, 8) void fused_kernel(
    const float* __restrict__ feat,
    const float* __restrict__ boxes,
    const int*   __restrict__ fidx,
    float*       __restrict__ out)
{
    extern __shared__ float sm[];

    if (blockIdx.x >= ROI_BLOCKS) {
        // ---------------- snode + fake_h_s branch (2 planes/warp) ---------
        const int warp = threadIdx.x >> 5;
        const int lane = threadIdx.x & 31;
        const size_t p0 = (size_t)(blockIdx.x - ROI_BLOCKS) * 16 + warp * 2;

        #pragma unroll
        for (int pp = 0; pp < 2; ++pp) {
            const size_t planeidx = p0 + pp;
            const float* src  = feat + planeidx * (HH*WW);
            float*       fake = out + FAKE_OFF + planeidx * 144;

            // ---- sum via float4 (196 floats = 49 float4, 16B aligned) ----
            const float4* s4 = (const float4*)src;
            float4 v = __ldg(s4 + lane);              // lane < 32 < 49
            float sum = (v.x + v.y) + (v.z + v.w);
            if (lane < 17) {
                float4 w = __ldg(s4 + lane + 32);
                sum += (w.x + w.y) + (w.z + w.w);
            }
            #pragma unroll
            for (int o = 16; o; o >>= 1)
                sum += __shfl_down_sync(0xFFFFFFFFu, sum, o);
            if (lane == 0)
                stcs1(out + SNODE_OFF + planeidx, sum * (1.0f / 196.0f));

            // ---- fake slice via 72 float2 units (12 rows x 6) ----
            #pragma unroll
            for (int k = 0; k < 3; ++k) {
                const int u = lane + k * 32;
                if (u < 72) {
                    const int row = u / 6;            // 0..11
                    const int cx  = (u - row * 6) * 2;  // 0,2,..,10
                    const int so  = (row + 1) * WW + 1 + cx;
                    float2 val;
                    val.x = __ldg(src + so);
                    val.y = __ldg(src + so + 1);
                    stcs2((float2*)(fake + row * 12 + cx), val);
                }
            }
        }
        return;
    }

    // -------------------------- RoI branch (4 boxes, sequential) -----------
    float* outsm = sm;                     // CHT * 49 floats (6,272 B)

    const int tid  = threadIdx.x;
    const int warp = tid >> 5, lane = tid & 31;
    const int quad = blockIdx.x / TILES;
    const int c0   = (blockIdx.x % TILES) * CHT;
    const int cw   = warp * 4;             // warp's first channel in tile

    #pragma unroll
    for (int i = 0; i < BOXPB; ++i)
        roi_one_box(feat, boxes, fidx, out, outsm, quad*BOXPB + i, c0, cw, lane);
}

// ---------------------------------------------------------------------------
extern "C" void kernel_launch(void* const* d_in, const int* in_sizes, int n_in,
                              void* d_out, int out_size)
{
    const float* feat  = (const float*)d_in[0];
    const float* boxes = (const float*)d_in[1];
    const int*   fidx  = (const int*)d_in[2];
    float*       out   = (float*)d_out;

    const int roi_smem = (CHT * OUTS * OUTS) * (int)sizeof(float); // 6,272 B
    cudaFuncSetAttribute(fused_kernel,
                         cudaFuncAttributeMaxDynamicSharedMemorySize, roi_smem);

    fused_kernel<<<ROI_BLOCKS + SNODE_BLOCKS, 256, roi_smem>>>(feat, boxes, fidx, out);
}